// round 5
// baseline (speedup 1.0000x reference)
#include <cuda_runtime.h>
#include <cstdint>

#define N_NODES  50000
#define N_EDGES  1600000
#define IN_CH    64
#define HID      16
#define NCLS     10
#define L2S      16   // padded row stride for layer-2 rows (64B)

// ---------------- scratch (device globals; no allocations allowed) ----------
__device__ __align__(16) float g_y1  [N_NODES * HID];   // x @ w_rel1
__device__ __align__(16) float g_agg1[N_NODES * HID];   // x @ w_root1 + b_rel1 (seed)
__device__ __align__(16) float g_y2  [N_NODES * L2S];   // h @ w_rel2 (cols 10..15 stay 0)
__device__ __align__(16) float g_agg2[N_NODES * L2S];   // h @ w_root2 + b_rel2 (seed)
__device__ int g_cnt[N_NODES];                          // per-dst degree histogram
__device__ int g_off[N_NODES + 1];                      // CSR offsets
__device__ int g_cur[N_NODES + 1];                      // permute cursors
__device__ int g_csr[N_EDGES];                          // src ids grouped by dst
__device__ int g_is64;                                  // edge_index dtype flag

// ---------------- kernel 1: layer-1 projections (4 threads / node) ----------
// sub: mat = sub>>1 (0: w_rel1 -> y1 ; 1: w_root1 + b -> agg1 seed)
//      half = sub&1 (output cols 8*half..8*half+7)
// Also: thread gid<N_NODES zeroes the histogram; block0/t0 probes dtype.
__global__ void layer1_node(const float* __restrict__ x,
                            const float* __restrict__ w_rel1,
                            const float* __restrict__ b_rel1,
                            const float* __restrict__ w_root1,
                            const int*   __restrict__ ei) {
    int gid = blockIdx.x * blockDim.x + threadIdx.x;
    if (gid == 0) {
        int all_zero = 1;
#pragma unroll
        for (int i = 0; i < 16; i++)
            if (ei[2 * i + 1] != 0) all_zero = 0;
        g_is64 = all_zero;   // int64 indices < 2^31 -> odd 32-bit words all zero
    }
    if (gid < N_NODES) g_cnt[gid] = 0;

    __shared__ float s_w[2][IN_CH * HID];
    __shared__ float s_b[HID];
    for (int i = threadIdx.x; i < IN_CH * HID; i += blockDim.x) {
        s_w[0][i] = w_rel1[i];
        s_w[1][i] = w_root1[i];
    }
    if (threadIdx.x < HID) s_b[threadIdx.x] = b_rel1[threadIdx.x];
    __syncthreads();

    int node = gid >> 2;
    if (node >= N_NODES) return;
    int sub  = gid & 3;
    int mat  = sub >> 1;
    int half = sub & 1;
    const float* w = s_w[mat] + half * 8;

    float acc[8];
#pragma unroll
    for (int j = 0; j < 8; j++) acc[j] = mat ? s_b[half * 8 + j] : 0.f;

    const float4* xr = reinterpret_cast<const float4*>(x + (size_t)node * IN_CH);
#pragma unroll
    for (int k4 = 0; k4 < IN_CH / 4; k4++) {
        float4 xv = __ldg(xr + k4);
        const float xs[4] = {xv.x, xv.y, xv.z, xv.w};
#pragma unroll
        for (int kk = 0; kk < 4; kk++) {
            float v = xs[kk];
            const float* wr = w + (k4 * 4 + kk) * HID;
#pragma unroll
            for (int j = 0; j < 8; j++) acc[j] = fmaf(v, wr[j], acc[j]);
        }
    }

    float* dstbuf = mat ? g_agg1 : g_y1;
    float4* op = reinterpret_cast<float4*>(dstbuf + (size_t)node * HID + half * 8);
    op[0] = make_float4(acc[0], acc[1], acc[2], acc[3]);
    op[1] = make_float4(acc[4], acc[5], acc[6], acc[7]);
}

// ---------------- kernel 2: dst histogram ------------------------------------
__global__ void hist_kernel(const int* __restrict__ ei) {
    int e = blockIdx.x * blockDim.x + threadIdx.x;
    if (e >= N_EDGES) return;
    int off = g_is64 ? 2 : 1;
    int dst = __ldg(ei + ((size_t)N_EDGES + e) * off);
    if ((unsigned)dst >= N_NODES) return;  // hardening
    atomicAdd(&g_cnt[dst], 1);
}

// ---------------- kernel 3: exclusive scan (1 block, 1024 threads) ----------
__global__ void scan_kernel() {
    __shared__ int s[1024];
    int tid = threadIdx.x;
    const int CH = (N_NODES + 1023) / 1024;          // 49
    int beg = tid * CH;
    int end = min(beg + CH, N_NODES);
    int sum = 0;
    for (int i = beg; i < end; i++) sum += g_cnt[i];
    s[tid] = sum;
    __syncthreads();
    for (int d = 1; d < 1024; d <<= 1) {
        int v = (tid >= d) ? s[tid - d] : 0;
        __syncthreads();
        s[tid] += v;
        __syncthreads();
    }
    int run = (tid > 0) ? s[tid - 1] : 0;            // exclusive prefix
    if (tid == 0) { g_off[0] = 0; g_cur[0] = 0; }
    for (int i = beg; i < end; i++) {
        run += g_cnt[i];
        g_off[i + 1] = run;
        g_cur[i + 1] = run;
    }
}

// ---------------- kernel 4: permute edges into CSR ---------------------------
__global__ void permute_kernel(const int* __restrict__ ei) {
    int e = blockIdx.x * blockDim.x + threadIdx.x;
    if (e >= N_EDGES) return;
    int off = g_is64 ? 2 : 1;
    int src = __ldg(ei + (size_t)e * off);
    int dst = __ldg(ei + ((size_t)N_EDGES + e) * off);
    if ((unsigned)src >= N_NODES || (unsigned)dst >= N_NODES) return;  // hardening
    int pos = atomicAdd(&g_cur[dst], 1);
    g_csr[pos] = src;
}

// ---------------- kernel 5: gather layer 1 + relu + layer-2 projections ------
// 16 threads per node; thread t owns column t. Per edge, the 16 lanes read one
// contiguous 64B row of y1 (coalesced). Then h is exchanged via shfl within the
// 16-lane group and the layer-2 dual GEMM is computed in-register.
__global__ void gather1_layer2(const float* __restrict__ w_rel2,
                               const float* __restrict__ b_rel2,
                               const float* __restrict__ w_root2) {
    __shared__ float s_wr[HID * NCLS];
    __shared__ float s_wo[HID * NCLS];
    __shared__ float s_b[NCLS];
    for (int i = threadIdx.x; i < HID * NCLS; i += blockDim.x) {
        s_wr[i] = w_rel2[i];
        s_wo[i] = w_root2[i];
    }
    if (threadIdx.x < NCLS) s_b[threadIdx.x] = b_rel2[threadIdx.x];
    __syncthreads();

    int gid  = blockIdx.x * blockDim.x + threadIdx.x;
    int node = gid >> 4;
    int t    = gid & 15;
    if (node >= N_NODES) return;   // never taken: grid covers exactly N_NODES*16

    int beg = __ldg(g_off + node);
    int end = __ldg(g_off + node + 1);

    float acc = 0.f;
    int j = beg;
    for (; j + 4 <= end; j += 4) {
        int s0 = __ldg(g_csr + j);
        int s1 = __ldg(g_csr + j + 1);
        int s2 = __ldg(g_csr + j + 2);
        int s3 = __ldg(g_csr + j + 3);
        float v0 = __ldg(g_y1 + (size_t)s0 * HID + t);
        float v1 = __ldg(g_y1 + (size_t)s1 * HID + t);
        float v2 = __ldg(g_y1 + (size_t)s2 * HID + t);
        float v3 = __ldg(g_y1 + (size_t)s3 * HID + t);
        acc += (v0 + v1) + (v2 + v3);
    }
    for (; j < end; j++)
        acc += __ldg(g_y1 + (size_t)__ldg(g_csr + j) * HID + t);

    // h_t = relu(root_seed + neighbor_sum)
    float h = fmaxf(g_agg1[(size_t)node * HID + t] + acc, 0.f);

    // layer-2 dual GEMM: thread t computes output column t (t<10 meaningful)
    float arel  = 0.f;
    float aroot = (t < NCLS) ? s_b[t] : 0.f;
#pragma unroll
    for (int k = 0; k < HID; k++) {
        float hk = __shfl_sync(0xFFFFFFFFu, h, k, 16);
        if (t < NCLS) {
            arel  = fmaf(hk, s_wr[k * NCLS + t], arel);
            aroot = fmaf(hk, s_wo[k * NCLS + t], aroot);
        }
    }
    if (t < NCLS) {
        g_y2  [(size_t)node * L2S + t] = arel;
        g_agg2[(size_t)node * L2S + t] = aroot;
    }
}

// ---------------- kernel 6: gather layer 2 + log_softmax ---------------------
// 16 threads per node; butterfly shuffles over the 16-lane group do the softmax.
__global__ void gather2_lsm(float* __restrict__ out) {
    int gid  = blockIdx.x * blockDim.x + threadIdx.x;
    int node = gid >> 4;
    int t    = gid & 15;
    if (node >= N_NODES) return;   // never taken

    int beg = __ldg(g_off + node);
    int end = __ldg(g_off + node + 1);

    float acc = 0.f;
    int j = beg;
    for (; j + 4 <= end; j += 4) {
        int s0 = __ldg(g_csr + j);
        int s1 = __ldg(g_csr + j + 1);
        int s2 = __ldg(g_csr + j + 2);
        int s3 = __ldg(g_csr + j + 3);
        float v0 = __ldg(g_y2 + (size_t)s0 * L2S + t);
        float v1 = __ldg(g_y2 + (size_t)s1 * L2S + t);
        float v2 = __ldg(g_y2 + (size_t)s2 * L2S + t);
        float v3 = __ldg(g_y2 + (size_t)s3 * L2S + t);
        acc += (v0 + v1) + (v2 + v3);
    }
    for (; j < end; j++)
        acc += __ldg(g_y2 + (size_t)__ldg(g_csr + j) * L2S + t);

    float val = (t < NCLS) ? (g_agg2[(size_t)node * L2S + t] + acc) : 0.f;

    // max over the 10 active lanes
    float m = (t < NCLS) ? val : -3.4e38f;
#pragma unroll
    for (int d = 8; d >= 1; d >>= 1)
        m = fmaxf(m, __shfl_xor_sync(0xFFFFFFFFu, m, d, 16));
    // sum of exp
    float e = (t < NCLS) ? __expf(val - m) : 0.f;
    float s = e;
#pragma unroll
    for (int d = 8; d >= 1; d >>= 1)
        s += __shfl_xor_sync(0xFFFFFFFFu, s, d, 16);
    float lse = __logf(s) + m;

    if (t < NCLS) out[(size_t)node * NCLS + t] = val - lse;
}

// ---------------- launch -----------------------------------------------------
extern "C" void kernel_launch(void* const* d_in, const int* in_sizes, int n_in,
                              void* d_out, int out_size) {
    const float* x       = (const float*)d_in[0];
    const int*   ei      = (const int*)d_in[1];   // dtype resolved by inline probe
    const float* w_rel1  = (const float*)d_in[2];
    const float* b_rel1  = (const float*)d_in[3];
    const float* w_root1 = (const float*)d_in[4];
    const float* w_rel2  = (const float*)d_in[5];
    const float* b_rel2  = (const float*)d_in[6];
    const float* w_root2 = (const float*)d_in[7];
    float* out = (float*)d_out;

    const int TB = 256;

    int l1blocks = (N_NODES * 4 + TB - 1) / TB;       // 4 threads / node
    layer1_node<<<l1blocks, TB>>>(x, w_rel1, b_rel1, w_root1, ei);

    int eblocks = (N_EDGES + TB - 1) / TB;            // 1 thread / edge
    hist_kernel<<<eblocks, TB>>>(ei);
    scan_kernel<<<1, 1024>>>();
    permute_kernel<<<eblocks, TB>>>(ei);

    int gblocks = (N_NODES * 16 + TB - 1) / TB;       // 16 threads / node (exact)
    gather1_layer2<<<gblocks, TB>>>(w_rel2, b_rel2, w_root2);
    gather2_lsm<<<gblocks, TB>>>(out);
}

// round 6
// speedup vs baseline: 1.5416x; 1.5416x over previous
#include <cuda_runtime.h>
#include <cstdint>

#define N_NODES  50000
#define N_EDGES  1600000
#define IN_CH    64
#define HID      16
#define NCLS     10
#define L2S      12   // layer-2 row stride: 48B rows, base 16B-aligned

// ---------------- scratch (device globals; no allocations allowed) ----------
__device__ __align__(16) float g_y1  [N_NODES * HID];   // x @ w_rel1
__device__ __align__(16) float g_agg1[N_NODES * HID];   // x @ w_root1 + b (seed, then += scatter)
__device__ __align__(16) float g_y2  [N_NODES * L2S];   // h @ w_rel2
__device__ __align__(16) float g_agg2[N_NODES * L2S];   // h @ w_root2 + b (seed, then += scatter)
__device__ int g_is64;                                  // edge_index dtype flag

// ---------------- vector reductions ------------------------------------------
__device__ __forceinline__ void red_add_v4(float* p, float4 v) {
    asm volatile("red.global.add.v4.f32 [%0], {%1,%2,%3,%4};"
                 :: "l"(p), "f"(v.x), "f"(v.y), "f"(v.z), "f"(v.w) : "memory");
}
__device__ __forceinline__ void red_add_v2(float* p, float2 v) {
    asm volatile("red.global.add.v2.f32 [%0], {%1,%2};"
                 :: "l"(p), "f"(v.x), "f"(v.y) : "memory");
}

// ---------------- kernel 1: layer-1 projections (4 threads / node) ----------
// sub: mat = sub>>1 (0: w_rel1 -> y1 ; 1: w_root1 + b -> agg1 seed)
//      half = sub&1 (output cols 8*half..8*half+7)
// Block0/t0 probes the edge_index dtype (int64 high words all zero).
__global__ void layer1_node(const float* __restrict__ x,
                            const float* __restrict__ w_rel1,
                            const float* __restrict__ b_rel1,
                            const float* __restrict__ w_root1,
                            const int*   __restrict__ ei) {
    int gid = blockIdx.x * blockDim.x + threadIdx.x;
    if (gid == 0) {
        int all_zero = 1;
#pragma unroll
        for (int i = 0; i < 16; i++)
            if (ei[2 * i + 1] != 0) all_zero = 0;
        g_is64 = all_zero;
    }

    __shared__ float s_w[2][IN_CH * HID];
    __shared__ float s_b[HID];
    for (int i = threadIdx.x; i < IN_CH * HID; i += blockDim.x) {
        s_w[0][i] = w_rel1[i];
        s_w[1][i] = w_root1[i];
    }
    if (threadIdx.x < HID) s_b[threadIdx.x] = b_rel1[threadIdx.x];
    __syncthreads();

    int node = gid >> 2;
    if (node >= N_NODES) return;
    int sub  = gid & 3;
    int mat  = sub >> 1;
    int half = sub & 1;
    const float* w = s_w[mat] + half * 8;

    float acc[8];
#pragma unroll
    for (int j = 0; j < 8; j++) acc[j] = mat ? s_b[half * 8 + j] : 0.f;

    const float4* xr = reinterpret_cast<const float4*>(x + (size_t)node * IN_CH);
#pragma unroll
    for (int k4 = 0; k4 < IN_CH / 4; k4++) {
        float4 xv = __ldg(xr + k4);
        const float xs[4] = {xv.x, xv.y, xv.z, xv.w};
#pragma unroll
        for (int kk = 0; kk < 4; kk++) {
            float v = xs[kk];
            const float* wr = w + (k4 * 4 + kk) * HID;
#pragma unroll
            for (int j = 0; j < 8; j++) acc[j] = fmaf(v, wr[j], acc[j]);
        }
    }

    float* dstbuf = mat ? g_agg1 : g_y1;
    float4* op = reinterpret_cast<float4*>(dstbuf + (size_t)node * HID + half * 8);
    op[0] = make_float4(acc[0], acc[1], acc[2], acc[3]);
    op[1] = make_float4(acc[4], acc[5], acc[6], acc[7]);
}

// ---------------- kernel 2: edge scatter, layer 1 (1 thread / edge) ----------
// 2 index LDG + 4x LDG.128 gather (MLP=4) + 4x RED.128.
__global__ void scatter1(const int* __restrict__ ei) {
    int e = blockIdx.x * blockDim.x + threadIdx.x;
    if (e >= N_EDGES) return;
    int off = g_is64 ? 2 : 1;                 // int64: read low words only
    int src = __ldg(ei + (size_t)e * off);
    int dst = __ldg(ei + ((size_t)N_EDGES + e) * off);
    if ((unsigned)src >= N_NODES || (unsigned)dst >= N_NODES) return;  // hardening
    const float4* yp = reinterpret_cast<const float4*>(g_y1 + (size_t)src * HID);
    float4 a0 = yp[0];
    float4 a1 = yp[1];
    float4 a2 = yp[2];
    float4 a3 = yp[3];
    float* ap = g_agg1 + (size_t)dst * HID;
    red_add_v4(ap,      a0);
    red_add_v4(ap + 4,  a1);
    red_add_v4(ap + 8,  a2);
    red_add_v4(ap + 12, a3);
}

// ---------------- kernel 3: relu + layer-2 projections (2 threads / node) ---
// mat = tid&1 : 0 -> y2 = h @ w_rel2 ; 1 -> agg2 = h @ w_root2 + b_rel2
__global__ void layer2_node(const float* __restrict__ w_rel2,
                            const float* __restrict__ b_rel2,
                            const float* __restrict__ w_root2) {
    __shared__ float s_w[2][HID * NCLS];
    __shared__ float s_b[NCLS];
    for (int i = threadIdx.x; i < HID * NCLS; i += blockDim.x) {
        s_w[0][i] = w_rel2[i];
        s_w[1][i] = w_root2[i];
    }
    if (threadIdx.x < NCLS) s_b[threadIdx.x] = b_rel2[threadIdx.x];
    __syncthreads();

    int gid  = blockIdx.x * blockDim.x + threadIdx.x;
    int node = gid >> 1;
    if (node >= N_NODES) return;
    int mat  = gid & 1;
    const float* w = s_w[mat];

    float h[HID];
    const float4* a1p = reinterpret_cast<const float4*>(g_agg1 + (size_t)node * HID);
#pragma unroll
    for (int j = 0; j < HID / 4; j++) {
        float4 v = a1p[j];
        h[4*j]   = fmaxf(v.x, 0.f);
        h[4*j+1] = fmaxf(v.y, 0.f);
        h[4*j+2] = fmaxf(v.z, 0.f);
        h[4*j+3] = fmaxf(v.w, 0.f);
    }

    float acc[NCLS];
#pragma unroll
    for (int j = 0; j < NCLS; j++) acc[j] = mat ? s_b[j] : 0.f;
#pragma unroll
    for (int k = 0; k < HID; k++) {
        float v = h[k];
#pragma unroll
        for (int j = 0; j < NCLS; j++) acc[j] = fmaf(v, w[k * NCLS + j], acc[j]);
    }

    float* dstbuf = mat ? g_agg2 : g_y2;
    float* op = dstbuf + (size_t)node * L2S;
    *reinterpret_cast<float4*>(op)     = make_float4(acc[0], acc[1], acc[2], acc[3]);
    *reinterpret_cast<float4*>(op + 4) = make_float4(acc[4], acc[5], acc[6], acc[7]);
    *reinterpret_cast<float2*>(op + 8) = make_float2(acc[8], acc[9]);
}

// ---------------- kernel 4: edge scatter, layer 2 (1 thread / edge) ----------
// 2 index LDG + v4/v4/v2 gather + v4/v4/v2 red.
__global__ void scatter2(const int* __restrict__ ei) {
    int e = blockIdx.x * blockDim.x + threadIdx.x;
    if (e >= N_EDGES) return;
    int off = g_is64 ? 2 : 1;
    int src = __ldg(ei + (size_t)e * off);
    int dst = __ldg(ei + ((size_t)N_EDGES + e) * off);
    if ((unsigned)src >= N_NODES || (unsigned)dst >= N_NODES) return;  // hardening
    const float* yp = g_y2 + (size_t)src * L2S;
    float4 a0 = *reinterpret_cast<const float4*>(yp);
    float4 a1 = *reinterpret_cast<const float4*>(yp + 4);
    float2 t  = *reinterpret_cast<const float2*>(yp + 8);
    float* ap = g_agg2 + (size_t)dst * L2S;
    red_add_v4(ap,     a0);
    red_add_v4(ap + 4, a1);
    red_add_v2(ap + 8, t);
}

// ---------------- kernel 5: log_softmax ------------------------------------
__global__ void lsm_kernel(float* __restrict__ out) {
    int node = blockIdx.x * blockDim.x + threadIdx.x;
    if (node >= N_NODES) return;
    const float* ap = g_agg2 + (size_t)node * L2S;
    float v[NCLS];
    float m = -3.4e38f;
#pragma unroll
    for (int j = 0; j < NCLS; j++) { v[j] = ap[j]; m = fmaxf(m, v[j]); }
    float s = 0.f;
#pragma unroll
    for (int j = 0; j < NCLS; j++) s += __expf(v[j] - m);
    float lse = __logf(s) + m;
    float* op = out + (size_t)node * NCLS;
#pragma unroll
    for (int j = 0; j < NCLS; j++) op[j] = v[j] - lse;
}

// ---------------- launch -----------------------------------------------------
extern "C" void kernel_launch(void* const* d_in, const int* in_sizes, int n_in,
                              void* d_out, int out_size) {
    const float* x       = (const float*)d_in[0];
    const int*   ei      = (const int*)d_in[1];   // dtype resolved by inline probe
    const float* w_rel1  = (const float*)d_in[2];
    const float* b_rel1  = (const float*)d_in[3];
    const float* w_root1 = (const float*)d_in[4];
    const float* w_rel2  = (const float*)d_in[5];
    const float* b_rel2  = (const float*)d_in[6];
    const float* w_root2 = (const float*)d_in[7];
    float* out = (float*)d_out;

    const int TB = 256;

    int l1blocks = (N_NODES * 4 + TB - 1) / TB;        // 4 threads / node
    layer1_node<<<l1blocks, TB>>>(x, w_rel1, b_rel1, w_root1, ei);

    int eblocks = (N_EDGES + TB - 1) / TB;             // 1 thread / edge
    scatter1<<<eblocks, TB>>>(ei);

    int l2blocks = (N_NODES * 2 + TB - 1) / TB;        // 2 threads / node
    layer2_node<<<l2blocks, TB>>>(w_rel2, b_rel2, w_root2);

    scatter2<<<eblocks, TB>>>(ei);

    int nodeBlocks = (N_NODES + TB - 1) / TB;
    lsm_kernel<<<nodeBlocks, TB>>>(out);
}

// round 7
// speedup vs baseline: 1.8429x; 1.1954x over previous
#include <cuda_runtime.h>
#include <cstdint>

#define N_NODES  50000
#define N_EDGES  1600000
#define IN_CH    64
#define HID      16
#define NCLS     10
#define L2S      16   // layer-2 row stride: 64B sector-aligned rows

// ---------------- scratch (device globals; no allocations allowed) ----------
__device__ __align__(32) float g_y1  [N_NODES * HID];   // x @ w_rel1
__device__ __align__(32) float g_agg1[N_NODES * HID];   // x @ w_root1 + b (seed, then += scatter)
__device__ __align__(32) float g_y2  [N_NODES * L2S];   // h @ w_rel2 (cols 10..15 unused)
__device__ __align__(32) float g_agg2[N_NODES * L2S];   // h @ w_root2 + b (seed, then += scatter)
__device__ int g_is64;                                  // edge_index dtype flag

// ---------------- vector reductions ------------------------------------------
__device__ __forceinline__ void red_add_v4(float* p, float4 v) {
    asm volatile("red.global.add.v4.f32 [%0], {%1,%2,%3,%4};"
                 :: "l"(p), "f"(v.x), "f"(v.y), "f"(v.z), "f"(v.w) : "memory");
}
__device__ __forceinline__ void red_add_v2(float* p, float2 v) {
    asm volatile("red.global.add.v2.f32 [%0], {%1,%2};"
                 :: "l"(p), "f"(v.x), "f"(v.y) : "memory");
}

// ---------------- kernel 1: layer-1 projections (4 threads / node) ----------
// sub: mat = sub>>1 (0: w_rel1 -> y1 ; 1: w_root1 + b -> agg1 seed)
//      half = sub&1 (output cols 8*half..8*half+7)
// Block0/t0 probes the edge_index dtype (int64 high words all zero).
__global__ void layer1_node(const float* __restrict__ x,
                            const float* __restrict__ w_rel1,
                            const float* __restrict__ b_rel1,
                            const float* __restrict__ w_root1,
                            const int*   __restrict__ ei) {
    int gid = blockIdx.x * blockDim.x + threadIdx.x;
    if (gid == 0) {
        int all_zero = 1;
#pragma unroll
        for (int i = 0; i < 16; i++)
            if (ei[2 * i + 1] != 0) all_zero = 0;
        g_is64 = all_zero;
    }

    __shared__ float s_w[2][IN_CH * HID];
    __shared__ float s_b[HID];
    for (int i = threadIdx.x; i < IN_CH * HID; i += blockDim.x) {
        s_w[0][i] = w_rel1[i];
        s_w[1][i] = w_root1[i];
    }
    if (threadIdx.x < HID) s_b[threadIdx.x] = b_rel1[threadIdx.x];
    __syncthreads();

    int node = gid >> 2;
    if (node >= N_NODES) return;
    int sub  = gid & 3;
    int mat  = sub >> 1;
    int half = sub & 1;
    const float* w = s_w[mat] + half * 8;

    float acc[8];
#pragma unroll
    for (int j = 0; j < 8; j++) acc[j] = mat ? s_b[half * 8 + j] : 0.f;

    const float4* xr = reinterpret_cast<const float4*>(x + (size_t)node * IN_CH);
#pragma unroll
    for (int k4 = 0; k4 < IN_CH / 4; k4++) {
        float4 xv = __ldg(xr + k4);
        const float xs[4] = {xv.x, xv.y, xv.z, xv.w};
#pragma unroll
        for (int kk = 0; kk < 4; kk++) {
            float v = xs[kk];
            const float* wr = w + (k4 * 4 + kk) * HID;
#pragma unroll
            for (int j = 0; j < 8; j++) acc[j] = fmaf(v, wr[j], acc[j]);
        }
    }

    float* dstbuf = mat ? g_agg1 : g_y1;
    float4* op = reinterpret_cast<float4*>(dstbuf + (size_t)node * HID + half * 8);
    op[0] = make_float4(acc[0], acc[1], acc[2], acc[3]);
    op[1] = make_float4(acc[4], acc[5], acc[6], acc[7]);
}

// ---------------- kernel 2: edge scatter, layer 1 (4 lanes / edge) -----------
// Lane q moves quarter q of the 64B row: gather and red both fully coalesced
// (4 consecutive lanes hit consecutive 16B of one row -> LTS sector-merges).
__global__ void scatter1(const int* __restrict__ ei) {
    int idx = blockIdx.x * blockDim.x + threadIdx.x;
    int e = idx >> 2;
    if (e >= N_EDGES) return;
    int q = idx & 3;
    int off = g_is64 ? 2 : 1;                 // int64: read low words only
    int src = __ldg(ei + (size_t)e * off);
    int dst = __ldg(ei + ((size_t)N_EDGES + e) * off);
    if ((unsigned)src >= N_NODES || (unsigned)dst >= N_NODES) return;  // hardening
    float4 v = *reinterpret_cast<const float4*>(g_y1 + (size_t)src * HID + q * 4);
    red_add_v4(g_agg1 + (size_t)dst * HID + q * 4, v);
}

// ---------------- kernel 3: relu + layer-2 projections (2 threads / node) ---
// mat = tid&1 : 0 -> y2 = h @ w_rel2 ; 1 -> agg2 = h @ w_root2 + b_rel2
__global__ void layer2_node(const float* __restrict__ w_rel2,
                            const float* __restrict__ b_rel2,
                            const float* __restrict__ w_root2) {
    __shared__ float s_w[2][HID * NCLS];
    __shared__ float s_b[NCLS];
    for (int i = threadIdx.x; i < HID * NCLS; i += blockDim.x) {
        s_w[0][i] = w_rel2[i];
        s_w[1][i] = w_root2[i];
    }
    if (threadIdx.x < NCLS) s_b[threadIdx.x] = b_rel2[threadIdx.x];
    __syncthreads();

    int gid  = blockIdx.x * blockDim.x + threadIdx.x;
    int node = gid >> 1;
    if (node >= N_NODES) return;
    int mat  = gid & 1;
    const float* w = s_w[mat];

    float h[HID];
    const float4* a1p = reinterpret_cast<const float4*>(g_agg1 + (size_t)node * HID);
#pragma unroll
    for (int j = 0; j < HID / 4; j++) {
        float4 v = a1p[j];
        h[4*j]   = fmaxf(v.x, 0.f);
        h[4*j+1] = fmaxf(v.y, 0.f);
        h[4*j+2] = fmaxf(v.z, 0.f);
        h[4*j+3] = fmaxf(v.w, 0.f);
    }

    float acc[NCLS];
#pragma unroll
    for (int j = 0; j < NCLS; j++) acc[j] = mat ? s_b[j] : 0.f;
#pragma unroll
    for (int k = 0; k < HID; k++) {
        float v = h[k];
#pragma unroll
        for (int j = 0; j < NCLS; j++) acc[j] = fmaf(v, w[k * NCLS + j], acc[j]);
    }

    float* dstbuf = mat ? g_agg2 : g_y2;
    float* op = dstbuf + (size_t)node * L2S;
    *reinterpret_cast<float4*>(op)     = make_float4(acc[0], acc[1], acc[2], acc[3]);
    *reinterpret_cast<float4*>(op + 4) = make_float4(acc[4], acc[5], acc[6], acc[7]);
    *reinterpret_cast<float2*>(op + 8) = make_float2(acc[8], acc[9]);
}

// ---------------- kernel 4: edge scatter, layer 2 (4 lanes / edge) -----------
// Lane 0: floats 0-3 (v4), lane 1: floats 4-7 (v4), lane 2: floats 8-9 (v2),
// lane 3: idle. 64B-aligned rows -> gather = 2 sectors, reds merge into 2
// sector-RMWs per edge.
__global__ void scatter2(const int* __restrict__ ei) {
    int idx = blockIdx.x * blockDim.x + threadIdx.x;
    int e = idx >> 2;
    if (e >= N_EDGES) return;
    int q = idx & 3;
    if (q == 3) return;
    int off = g_is64 ? 2 : 1;
    int src = __ldg(ei + (size_t)e * off);
    int dst = __ldg(ei + ((size_t)N_EDGES + e) * off);
    if ((unsigned)src >= N_NODES || (unsigned)dst >= N_NODES) return;  // hardening
    const float* yp = g_y2   + (size_t)src * L2S;
    float*       ap = g_agg2 + (size_t)dst * L2S;
    if (q < 2) {
        float4 v = *reinterpret_cast<const float4*>(yp + q * 4);
        red_add_v4(ap + q * 4, v);
    } else {
        float2 v = *reinterpret_cast<const float2*>(yp + 8);
        red_add_v2(ap + 8, v);
    }
}

// ---------------- kernel 5: log_softmax ------------------------------------
__global__ void lsm_kernel(float* __restrict__ out) {
    int node = blockIdx.x * blockDim.x + threadIdx.x;
    if (node >= N_NODES) return;
    const float* ap = g_agg2 + (size_t)node * L2S;
    float v[NCLS];
    float m = -3.4e38f;
#pragma unroll
    for (int j = 0; j < NCLS; j++) { v[j] = ap[j]; m = fmaxf(m, v[j]); }
    float s = 0.f;
#pragma unroll
    for (int j = 0; j < NCLS; j++) s += __expf(v[j] - m);
    float lse = __logf(s) + m;
    float* op = out + (size_t)node * NCLS;
#pragma unroll
    for (int j = 0; j < NCLS; j++) op[j] = v[j] - lse;
}

// ---------------- launch -----------------------------------------------------
extern "C" void kernel_launch(void* const* d_in, const int* in_sizes, int n_in,
                              void* d_out, int out_size) {
    const float* x       = (const float*)d_in[0];
    const int*   ei      = (const int*)d_in[1];   // dtype resolved by inline probe
    const float* w_rel1  = (const float*)d_in[2];
    const float* b_rel1  = (const float*)d_in[3];
    const float* w_root1 = (const float*)d_in[4];
    const float* w_rel2  = (const float*)d_in[5];
    const float* b_rel2  = (const float*)d_in[6];
    const float* w_root2 = (const float*)d_in[7];
    float* out = (float*)d_out;

    const int TB = 256;

    int l1blocks = (N_NODES * 4 + TB - 1) / TB;        // 4 threads / node
    layer1_node<<<l1blocks, TB>>>(x, w_rel1, b_rel1, w_root1, ei);

    long long ethreads = (long long)N_EDGES * 4;       // 4 lanes / edge
    int eblocks = (int)((ethreads + TB - 1) / TB);
    scatter1<<<eblocks, TB>>>(ei);

    int l2blocks = (N_NODES * 2 + TB - 1) / TB;        // 2 threads / node
    layer2_node<<<l2blocks, TB>>>(w_rel2, b_rel2, w_root2);

    scatter2<<<eblocks, TB>>>(ei);

    int nodeBlocks = (N_NODES + TB - 1) / TB;
    lsm_kernel<<<nodeBlocks, TB>>>(out);
}

// round 9
// speedup vs baseline: 1.9997x; 1.0851x over previous
#include <cuda_runtime.h>
#include <cstdint>

#define N_NODES  50000
#define N_EDGES  1600000
#define IN_CH    64
#define HID      16
#define NCLS     10
#define L2S      16   // layer-2 row stride: 64B sector-aligned rows (cols 10-15 zero)

// ---------------- scratch (device globals; no allocations allowed) ----------
__device__ __align__(32) float g_y1  [N_NODES * HID];   // x @ w_rel1
__device__ __align__(32) float g_agg1[N_NODES * HID];   // x @ w_root1 + b (seed, then += scatter)
__device__ __align__(32) float g_y2  [N_NODES * L2S];   // h @ w_rel2, cols 10-15 = 0
__device__ __align__(32) float g_agg2[N_NODES * L2S];   // h @ w_root2 + b, cols 10-15 = 0
__device__ int g_is64;                                  // edge_index dtype flag

// ---------------- vector reduction -------------------------------------------
__device__ __forceinline__ void red_add_v4(float* p, float4 v) {
    asm volatile("red.global.add.v4.f32 [%0], {%1,%2,%3,%4};"
                 :: "l"(p), "f"(v.x), "f"(v.y), "f"(v.z), "f"(v.w) : "memory");
}

// ---------------- kernel 1: layer-1 projections (4 threads / node) ----------
// sub: mat = sub>>1 (0: w_rel1 -> y1 ; 1: w_root1 + b -> agg1 seed)
//      half = sub&1 (output cols 8*half..8*half+7)
// Block0/t0 probes the edge_index dtype (int64 high words all zero).
__global__ void layer1_node(const float* __restrict__ x,
                            const float* __restrict__ w_rel1,
                            const float* __restrict__ b_rel1,
                            const float* __restrict__ w_root1,
                            const int*   __restrict__ ei) {
    int gid = blockIdx.x * blockDim.x + threadIdx.x;
    if (gid == 0) {
        int all_zero = 1;
#pragma unroll
        for (int i = 0; i < 16; i++)
            if (ei[2 * i + 1] != 0) all_zero = 0;
        g_is64 = all_zero;
    }

    __shared__ float s_w[2][IN_CH * HID];
    __shared__ float s_b[HID];
    for (int i = threadIdx.x; i < IN_CH * HID; i += blockDim.x) {
        s_w[0][i] = w_rel1[i];
        s_w[1][i] = w_root1[i];
    }
    if (threadIdx.x < HID) s_b[threadIdx.x] = b_rel1[threadIdx.x];
    __syncthreads();

    int node = gid >> 2;
    if (node >= N_NODES) return;
    int sub  = gid & 3;
    int mat  = sub >> 1;
    int half = sub & 1;
    const float* w = s_w[mat] + half * 8;

    float acc[8];
#pragma unroll
    for (int j = 0; j < 8; j++) acc[j] = mat ? s_b[half * 8 + j] : 0.f;

    const float4* xr = reinterpret_cast<const float4*>(x + (size_t)node * IN_CH);
#pragma unroll
    for (int k4 = 0; k4 < IN_CH / 4; k4++) {
        float4 xv = __ldg(xr + k4);
        const float xs[4] = {xv.x, xv.y, xv.z, xv.w};
#pragma unroll
        for (int kk = 0; kk < 4; kk++) {
            float v = xs[kk];
            const float* wr = w + (k4 * 4 + kk) * HID;
#pragma unroll
            for (int j = 0; j < 8; j++) acc[j] = fmaf(v, wr[j], acc[j]);
        }
    }

    float* dstbuf = mat ? g_agg1 : g_y1;
    float4* op = reinterpret_cast<float4*>(dstbuf + (size_t)node * HID + half * 8);
    op[0] = make_float4(acc[0], acc[1], acc[2], acc[3]);
    op[1] = make_float4(acc[4], acc[5], acc[6], acc[7]);
}

// ---------------- kernel 2: edge scatter, layer 1 ----------------------------
// 4-lane groups, 2 edges per group. Lane q moves quarter q (16B) of the 64B row
// for both edges: uniform v4 gather + v4 red, two independent chains (MLP=2).
__global__ void scatter1(const int* __restrict__ ei) {
    int gid  = blockIdx.x * blockDim.x + threadIdx.x;
    int q    = gid & 3;
    int pair = gid >> 2;
    int e0   = pair * 2;
    if (e0 >= N_EDGES) return;
    int e1   = e0 + 1;                         // N_EDGES even -> always valid
    int off  = g_is64 ? 2 : 1;                 // int64: read low words only
    int s0 = __ldg(ei + (size_t)e0 * off);
    int d0 = __ldg(ei + ((size_t)N_EDGES + e0) * off);
    int s1 = __ldg(ei + (size_t)e1 * off);
    int d1 = __ldg(ei + ((size_t)N_EDGES + e1) * off);
    bool ok0 = (unsigned)s0 < N_NODES && (unsigned)d0 < N_NODES;  // hardening
    bool ok1 = (unsigned)s1 < N_NODES && (unsigned)d1 < N_NODES;
    if (ok0 & ok1) {
        float4 v0 = *reinterpret_cast<const float4*>(g_y1 + (size_t)s0 * HID + q * 4);
        float4 v1 = *reinterpret_cast<const float4*>(g_y1 + (size_t)s1 * HID + q * 4);
        red_add_v4(g_agg1 + (size_t)d0 * HID + q * 4, v0);
        red_add_v4(g_agg1 + (size_t)d1 * HID + q * 4, v1);
    } else {
        if (ok0) {
            float4 v0 = *reinterpret_cast<const float4*>(g_y1 + (size_t)s0 * HID + q * 4);
            red_add_v4(g_agg1 + (size_t)d0 * HID + q * 4, v0);
        }
        if (ok1) {
            float4 v1 = *reinterpret_cast<const float4*>(g_y1 + (size_t)s1 * HID + q * 4);
            red_add_v4(g_agg1 + (size_t)d1 * HID + q * 4, v1);
        }
    }
}

// ---------------- kernel 3: relu + layer-2 projections (2 threads / node) ---
// mat = tid&1 : 0 -> y2 = h @ w_rel2 ; 1 -> agg2 = h @ w_root2 + b_rel2
// Writes full 16-float rows; cols 10-15 zeroed so scatter2 lanes are uniform.
__global__ void layer2_node(const float* __restrict__ w_rel2,
                            const float* __restrict__ b_rel2,
                            const float* __restrict__ w_root2) {
    __shared__ float s_w[2][HID * NCLS];
    __shared__ float s_b[NCLS];
    for (int i = threadIdx.x; i < HID * NCLS; i += blockDim.x) {
        s_w[0][i] = w_rel2[i];
        s_w[1][i] = w_root2[i];
    }
    if (threadIdx.x < NCLS) s_b[threadIdx.x] = b_rel2[threadIdx.x];
    __syncthreads();

    int gid  = blockIdx.x * blockDim.x + threadIdx.x;
    int node = gid >> 1;
    if (node >= N_NODES) return;
    int mat  = gid & 1;
    const float* w = s_w[mat];

    float h[HID];
    const float4* a1p = reinterpret_cast<const float4*>(g_agg1 + (size_t)node * HID);
#pragma unroll
    for (int j = 0; j < HID / 4; j++) {
        float4 v = a1p[j];
        h[4*j]   = fmaxf(v.x, 0.f);
        h[4*j+1] = fmaxf(v.y, 0.f);
        h[4*j+2] = fmaxf(v.z, 0.f);
        h[4*j+3] = fmaxf(v.w, 0.f);
    }

    float acc[NCLS];
#pragma unroll
    for (int j = 0; j < NCLS; j++) acc[j] = mat ? s_b[j] : 0.f;
#pragma unroll
    for (int k = 0; k < HID; k++) {
        float v = h[k];
#pragma unroll
        for (int j = 0; j < NCLS; j++) acc[j] = fmaf(v, w[k * NCLS + j], acc[j]);
    }

    float* dstbuf = mat ? g_agg2 : g_y2;
    float4* op = reinterpret_cast<float4*>(dstbuf + (size_t)node * L2S);
    op[0] = make_float4(acc[0], acc[1], acc[2], acc[3]);
    op[1] = make_float4(acc[4], acc[5], acc[6], acc[7]);
    op[2] = make_float4(acc[8], acc[9], 0.f, 0.f);
    op[3] = make_float4(0.f, 0.f, 0.f, 0.f);
}

// ---------------- kernel 4: edge scatter, layer 2 ----------------------------
// Identical shape to scatter1: 4-lane groups x 2 edges, uniform v4 on 64B rows.
// Lanes 2-3 move the zero-padded tail of sector 1 (no extra sector cost).
__global__ void scatter2(const int* __restrict__ ei) {
    int gid  = blockIdx.x * blockDim.x + threadIdx.x;
    int q    = gid & 3;
    int pair = gid >> 2;
    int e0   = pair * 2;
    if (e0 >= N_EDGES) return;
    int e1   = e0 + 1;
    int off  = g_is64 ? 2 : 1;
    int s0 = __ldg(ei + (size_t)e0 * off);
    int d0 = __ldg(ei + ((size_t)N_EDGES + e0) * off);
    int s1 = __ldg(ei + (size_t)e1 * off);
    int d1 = __ldg(ei + ((size_t)N_EDGES + e1) * off);
    bool ok0 = (unsigned)s0 < N_NODES && (unsigned)d0 < N_NODES;  // hardening
    bool ok1 = (unsigned)s1 < N_NODES && (unsigned)d1 < N_NODES;
    if (ok0 & ok1) {
        float4 v0 = *reinterpret_cast<const float4*>(g_y2 + (size_t)s0 * L2S + q * 4);
        float4 v1 = *reinterpret_cast<const float4*>(g_y2 + (size_t)s1 * L2S + q * 4);
        red_add_v4(g_agg2 + (size_t)d0 * L2S + q * 4, v0);
        red_add_v4(g_agg2 + (size_t)d1 * L2S + q * 4, v1);
    } else {
        if (ok0) {
            float4 v0 = *reinterpret_cast<const float4*>(g_y2 + (size_t)s0 * L2S + q * 4);
            red_add_v4(g_agg2 + (size_t)d0 * L2S + q * 4, v0);
        }
        if (ok1) {
            float4 v1 = *reinterpret_cast<const float4*>(g_y2 + (size_t)s1 * L2S + q * 4);
            red_add_v4(g_agg2 + (size_t)d1 * L2S + q * 4, v1);
        }
    }
}

// ---------------- kernel 5: log_softmax ------------------------------------
__global__ void lsm_kernel(float* __restrict__ out) {
    int node = blockIdx.x * blockDim.x + threadIdx.x;
    if (node >= N_NODES) return;
    const float* ap = g_agg2 + (size_t)node * L2S;
    float v[NCLS];
    float m = -3.4e38f;
#pragma unroll
    for (int j = 0; j < NCLS; j++) { v[j] = ap[j]; m = fmaxf(m, v[j]); }
    float s = 0.f;
#pragma unroll
    for (int j = 0; j < NCLS; j++) s += __expf(v[j] - m);
    float lse = __logf(s) + m;
    float* op = out + (size_t)node * NCLS;
#pragma unroll
    for (int j = 0; j < NCLS; j++) op[j] = v[j] - lse;
}

// ---------------- launch -----------------------------------------------------
extern "C" void kernel_launch(void* const* d_in, const int* in_sizes, int n_in,
                              void* d_out, int out_size) {
    const float* x       = (const float*)d_in[0];
    const int*   ei      = (const int*)d_in[1];   // dtype resolved by inline probe
    const float* w_rel1  = (const float*)d_in[2];
    const float* b_rel1  = (const float*)d_in[3];
    const float* w_root1 = (const float*)d_in[4];
    const float* w_rel2  = (const float*)d_in[5];
    const float* b_rel2  = (const float*)d_in[6];
    const float* w_root2 = (const float*)d_in[7];
    float* out = (float*)d_out;

    const int TB = 256;

    int l1blocks = (N_NODES * 4 + TB - 1) / TB;        // 4 threads / node
    layer1_node<<<l1blocks, TB>>>(x, w_rel1, b_rel1, w_root1, ei);

    long long ethreads = (long long)(N_EDGES / 2) * 4; // 4 lanes x (E/2) groups
    int eblocks = (int)((ethreads + TB - 1) / TB);
    scatter1<<<eblocks, TB>>>(ei);

    int l2blocks = (N_NODES * 2 + TB - 1) / TB;        // 2 threads / node
    layer2_node<<<l2blocks, TB>>>(w_rel2, b_rel2, w_root2);

    scatter2<<<eblocks, TB>>>(ei);

    int nodeBlocks = (N_NODES + TB - 1) / TB;
    lsm_kernel<<<nodeBlocks, TB>>>(out);
}

// round 10
// speedup vs baseline: 2.0431x; 1.0217x over previous
#include <cuda_runtime.h>
#include <cstdint>

#define N_NODES  50000
#define N_EDGES  1600000
#define IN_CH    64
#define HID      16
#define NCLS     10
#define L2S      16   // layer-2 row stride: 64B sector-aligned rows (cols 10-15 zero)

// ---------------- scratch (device globals; no allocations allowed) ----------
__device__ __align__(32) float g_y1  [N_NODES * HID];   // x @ w_rel1
__device__ __align__(32) float g_agg1[N_NODES * HID];   // x @ w_root1 + b (seed, then += scatter)
__device__ __align__(32) float g_y2  [N_NODES * L2S];   // h @ w_rel2, cols 10-15 = 0
__device__ __align__(32) float g_agg2[N_NODES * L2S];   // h @ w_root2 + b, cols 10-15 = 0
__device__ int g_is64;                                  // edge_index dtype flag

// ---------------- vector reduction -------------------------------------------
__device__ __forceinline__ void red_add_v4(float* p, float4 v) {
    asm volatile("red.global.add.v4.f32 [%0], {%1,%2,%3,%4};"
                 :: "l"(p), "f"(v.x), "f"(v.y), "f"(v.z), "f"(v.w) : "memory");
}

// Branch-free clamp (indices are valid; clamp only guards a wrong dtype probe,
// which would then surface as rel_err, not a fault).
__device__ __forceinline__ int clampN(int v) {
    return (int)min((unsigned)v, (unsigned)(N_NODES - 1));
}

// Fetch 4 consecutive edge srcs (or dsts) starting at base (base % 4 == 0).
// int32: one int4 load. int64: two longlong2 loads, low words.
__device__ __forceinline__ int4 load_idx4(const int* ei, int is64, int base) {
    if (!is64) {
        return __ldg(reinterpret_cast<const int4*>(ei + base));
    } else {
        const longlong2* p = reinterpret_cast<const longlong2*>(ei) + (base >> 1);
        longlong2 a = __ldg(p);
        longlong2 b = __ldg(p + 1);
        return make_int4((int)a.x, (int)a.y, (int)b.x, (int)b.y);
    }
}

// ---------------- kernel 1: layer-1 projections (4 threads / node) ----------
// sub: mat = sub>>1 (0: w_rel1 -> y1 ; 1: w_root1 + b -> agg1 seed)
//      half = sub&1 (output cols 8*half..8*half+7)
// Block0/t0 probes the edge_index dtype (int64 high words all zero).
__global__ void layer1_node(const float* __restrict__ x,
                            const float* __restrict__ w_rel1,
                            const float* __restrict__ b_rel1,
                            const float* __restrict__ w_root1,
                            const int*   __restrict__ ei) {
    int gid = blockIdx.x * blockDim.x + threadIdx.x;
    if (gid == 0) {
        int all_zero = 1;
#pragma unroll
        for (int i = 0; i < 16; i++)
            if (ei[2 * i + 1] != 0) all_zero = 0;
        g_is64 = all_zero;
    }

    __shared__ float s_w[2][IN_CH * HID];
    __shared__ float s_b[HID];
    for (int i = threadIdx.x; i < IN_CH * HID; i += blockDim.x) {
        s_w[0][i] = w_rel1[i];
        s_w[1][i] = w_root1[i];
    }
    if (threadIdx.x < HID) s_b[threadIdx.x] = b_rel1[threadIdx.x];
    __syncthreads();

    int node = gid >> 2;
    if (node >= N_NODES) return;
    int sub  = gid & 3;
    int mat  = sub >> 1;
    int half = sub & 1;
    const float* w = s_w[mat] + half * 8;

    float acc[8];
#pragma unroll
    for (int j = 0; j < 8; j++) acc[j] = mat ? s_b[half * 8 + j] : 0.f;

    const float4* xr = reinterpret_cast<const float4*>(x + (size_t)node * IN_CH);
#pragma unroll
    for (int k4 = 0; k4 < IN_CH / 4; k4++) {
        float4 xv = __ldg(xr + k4);
        const float xs[4] = {xv.x, xv.y, xv.z, xv.w};
#pragma unroll
        for (int kk = 0; kk < 4; kk++) {
            float v = xs[kk];
            const float* wr = w + (k4 * 4 + kk) * HID;
#pragma unroll
            for (int j = 0; j < 8; j++) acc[j] = fmaf(v, wr[j], acc[j]);
        }
    }

    float* dstbuf = mat ? g_agg1 : g_y1;
    float4* op = reinterpret_cast<float4*>(dstbuf + (size_t)node * HID + half * 8);
    op[0] = make_float4(acc[0], acc[1], acc[2], acc[3]);
    op[1] = make_float4(acc[4], acc[5], acc[6], acc[7]);
}

// ---------------- kernel 2: edge scatter, layer 1 ----------------------------
// 4-lane groups x 4 edges. Lane q owns quarter q (16B) of each 64B row.
// Indices fetched as int4 (1 line per warp), 4 independent gather->red chains.
__global__ void scatter1(const int* __restrict__ ei) {
    int gid  = blockIdx.x * blockDim.x + threadIdx.x;
    int q4   = (gid & 3) * 4;
    int base = (gid >> 2) * 4;
    if (base >= N_EDGES) return;              // N_EDGES % 4 == 0, no tail
    int is64 = g_is64;
    int4 sv = load_idx4(ei, is64, base);
    int4 dv = load_idx4(ei, is64, N_EDGES * (is64 ? 1 : 1) + base); // dst block starts at element N_EDGES
    // NOTE: for int64 the dst block starts at int64-element N_EDGES as well;
    // load_idx4 indexes in *elements* of the active dtype.
    int s0 = clampN(sv.x), s1 = clampN(sv.y), s2 = clampN(sv.z), s3 = clampN(sv.w);
    int d0 = clampN(dv.x), d1 = clampN(dv.y), d2 = clampN(dv.z), d3 = clampN(dv.w);
    float4 v0 = *reinterpret_cast<const float4*>(g_y1 + (size_t)s0 * HID + q4);
    float4 v1 = *reinterpret_cast<const float4*>(g_y1 + (size_t)s1 * HID + q4);
    float4 v2 = *reinterpret_cast<const float4*>(g_y1 + (size_t)s2 * HID + q4);
    float4 v3 = *reinterpret_cast<const float4*>(g_y1 + (size_t)s3 * HID + q4);
    red_add_v4(g_agg1 + (size_t)d0 * HID + q4, v0);
    red_add_v4(g_agg1 + (size_t)d1 * HID + q4, v1);
    red_add_v4(g_agg1 + (size_t)d2 * HID + q4, v2);
    red_add_v4(g_agg1 + (size_t)d3 * HID + q4, v3);
}

// ---------------- kernel 3: relu + layer-2 projections (2 threads / node) ---
// mat = tid&1 : 0 -> y2 = h @ w_rel2 ; 1 -> agg2 = h @ w_root2 + b_rel2
// Writes full 16-float rows; cols 10-15 zeroed so scatter2 lanes are uniform.
__global__ void layer2_node(const float* __restrict__ w_rel2,
                            const float* __restrict__ b_rel2,
                            const float* __restrict__ w_root2) {
    __shared__ float s_w[2][HID * NCLS];
    __shared__ float s_b[NCLS];
    for (int i = threadIdx.x; i < HID * NCLS; i += blockDim.x) {
        s_w[0][i] = w_rel2[i];
        s_w[1][i] = w_root2[i];
    }
    if (threadIdx.x < NCLS) s_b[threadIdx.x] = b_rel2[threadIdx.x];
    __syncthreads();

    int gid  = blockIdx.x * blockDim.x + threadIdx.x;
    int node = gid >> 1;
    if (node >= N_NODES) return;
    int mat  = gid & 1;
    const float* w = s_w[mat];

    float h[HID];
    const float4* a1p = reinterpret_cast<const float4*>(g_agg1 + (size_t)node * HID);
#pragma unroll
    for (int j = 0; j < HID / 4; j++) {
        float4 v = a1p[j];
        h[4*j]   = fmaxf(v.x, 0.f);
        h[4*j+1] = fmaxf(v.y, 0.f);
        h[4*j+2] = fmaxf(v.z, 0.f);
        h[4*j+3] = fmaxf(v.w, 0.f);
    }

    float acc[NCLS];
#pragma unroll
    for (int j = 0; j < NCLS; j++) acc[j] = mat ? s_b[j] : 0.f;
#pragma unroll
    for (int k = 0; k < HID; k++) {
        float v = h[k];
#pragma unroll
        for (int j = 0; j < NCLS; j++) acc[j] = fmaf(v, w[k * NCLS + j], acc[j]);
    }

    float* dstbuf = mat ? g_agg2 : g_y2;
    float4* op = reinterpret_cast<float4*>(dstbuf + (size_t)node * L2S);
    op[0] = make_float4(acc[0], acc[1], acc[2], acc[3]);
    op[1] = make_float4(acc[4], acc[5], acc[6], acc[7]);
    op[2] = make_float4(acc[8], acc[9], 0.f, 0.f);
    op[3] = make_float4(0.f, 0.f, 0.f, 0.f);
}

// ---------------- kernel 4: edge scatter, layer 2 ----------------------------
// Same shape as scatter1 on the zero-padded 64B y2/agg2 rows.
__global__ void scatter2(const int* __restrict__ ei) {
    int gid  = blockIdx.x * blockDim.x + threadIdx.x;
    int q4   = (gid & 3) * 4;
    int base = (gid >> 2) * 4;
    if (base >= N_EDGES) return;
    int is64 = g_is64;
    int4 sv = load_idx4(ei, is64, base);
    int4 dv = load_idx4(ei, is64, N_EDGES + base);
    int s0 = clampN(sv.x), s1 = clampN(sv.y), s2 = clampN(sv.z), s3 = clampN(sv.w);
    int d0 = clampN(dv.x), d1 = clampN(dv.y), d2 = clampN(dv.z), d3 = clampN(dv.w);
    float4 v0 = *reinterpret_cast<const float4*>(g_y2 + (size_t)s0 * L2S + q4);
    float4 v1 = *reinterpret_cast<const float4*>(g_y2 + (size_t)s1 * L2S + q4);
    float4 v2 = *reinterpret_cast<const float4*>(g_y2 + (size_t)s2 * L2S + q4);
    float4 v3 = *reinterpret_cast<const float4*>(g_y2 + (size_t)s3 * L2S + q4);
    red_add_v4(g_agg2 + (size_t)d0 * L2S + q4, v0);
    red_add_v4(g_agg2 + (size_t)d1 * L2S + q4, v1);
    red_add_v4(g_agg2 + (size_t)d2 * L2S + q4, v2);
    red_add_v4(g_agg2 + (size_t)d3 * L2S + q4, v3);
}

// ---------------- kernel 5: log_softmax ------------------------------------
__global__ void lsm_kernel(float* __restrict__ out) {
    int node = blockIdx.x * blockDim.x + threadIdx.x;
    if (node >= N_NODES) return;
    const float* ap = g_agg2 + (size_t)node * L2S;
    float v[NCLS];
    float m = -3.4e38f;
#pragma unroll
    for (int j = 0; j < NCLS; j++) { v[j] = ap[j]; m = fmaxf(m, v[j]); }
    float s = 0.f;
#pragma unroll
    for (int j = 0; j < NCLS; j++) s += __expf(v[j] - m);
    float lse = __logf(s) + m;
    float* op = out + (size_t)node * NCLS;
#pragma unroll
    for (int j = 0; j < NCLS; j++) op[j] = v[j] - lse;
}

// ---------------- launch -----------------------------------------------------
extern "C" void kernel_launch(void* const* d_in, const int* in_sizes, int n_in,
                              void* d_out, int out_size) {
    const float* x       = (const float*)d_in[0];
    const int*   ei      = (const int*)d_in[1];   // dtype resolved by inline probe
    const float* w_rel1  = (const float*)d_in[2];
    const float* b_rel1  = (const float*)d_in[3];
    const float* w_root1 = (const float*)d_in[4];
    const float* w_rel2  = (const float*)d_in[5];
    const float* b_rel2  = (const float*)d_in[6];
    const float* w_root2 = (const float*)d_in[7];
    float* out = (float*)d_out;

    const int TB = 256;

    int l1blocks = (N_NODES * 4 + TB - 1) / TB;        // 4 threads / node
    layer1_node<<<l1blocks, TB>>>(x, w_rel1, b_rel1, w_root1, ei);

    long long ethreads = (long long)(N_EDGES / 4) * 4; // 4 lanes x (E/4) groups
    int eblocks = (int)((ethreads + TB - 1) / TB);
    scatter1<<<eblocks, TB>>>(ei);

    int l2blocks = (N_NODES * 2 + TB - 1) / TB;        // 2 threads / node
    layer2_node<<<l2blocks, TB>>>(w_rel2, b_rel2, w_root2);

    scatter2<<<eblocks, TB>>>(ei);

    int nodeBlocks = (N_NODES + TB - 1) / TB;
    lsm_kernel<<<nodeBlocks, TB>>>(out);
}